// round 7
// baseline (speedup 1.0000x reference)
#include <cuda_runtime.h>
#include <stdint.h>

#define HH 2048
#define WW 2048
#define NPIX (HH * WW)

#define TW 32                    // tile width
#define TH 16                    // tile height
#define SW (TW + 2)              // 34 (halo)
#define SH (TH + 2)              // 18 (halo)
#define NSLOT (SW * SH)          // 612
#define NRING (2 * SW + 2 * (SH - 2))   // 100 ring slots

#define NBX 64                   // tiles per row (bits in a mask word)
#define NBY 128                  // tile rows
#define NB  (NBX * NBY)          // 8192
#define TILES_PER_BLOCK 4
#define STEP_GRID (NB / TILES_PER_BLOCK)   // 2048

typedef unsigned long long ull;

__device__ float g_scratch[NPIX];
__device__ ull g_chmask[3][NBY];   // changed bits, 3-parity rotation
__device__ ull g_posmask[NBY];     // possible bits
__device__ ull g_zeromask[NBY];    // bit=1 -> tile is all-zero (x monotone: 1->0 only)

// ---------------------------------------------------------------------------
// Threefry-2x32, 20 rounds — exact transcription of jax._src.prng
// ---------------------------------------------------------------------------
__host__ __device__ __forceinline__ uint32_t rotl32(uint32_t v, uint32_t r) {
#ifdef __CUDA_ARCH__
    return __funnelshift_l(v, v, r);
#else
    return (v << r) | (v >> (32u - r));
#endif
}

__host__ __device__ __forceinline__ void tf2x32(uint32_t k0, uint32_t k1,
                                                uint32_t x0, uint32_t x1,
                                                uint32_t& o0, uint32_t& o1) {
    uint32_t ks2 = k0 ^ k1 ^ 0x1BD11BDAu;
    x0 += k0; x1 += k1;
#define TF_R(r) { x0 += x1; x1 = rotl32(x1, r); x1 ^= x0; }
    TF_R(13u) TF_R(15u) TF_R(26u) TF_R(6u)
    x0 += k1;  x1 += ks2 + 1u;
    TF_R(17u) TF_R(29u) TF_R(16u) TF_R(24u)
    x0 += ks2; x1 += k0 + 2u;
    TF_R(13u) TF_R(15u) TF_R(26u) TF_R(6u)
    x0 += k0;  x1 += k1 + 3u;
    TF_R(17u) TF_R(29u) TF_R(16u) TF_R(24u)
    x0 += k1;  x1 += ks2 + 4u;
    TF_R(13u) TF_R(15u) TF_R(26u) TF_R(6u)
    x0 += ks2; x1 += k0 + 5u;
#undef TF_R
    o0 = x0; o1 = x1;
}

// Partitionable-mode random bits for flat index p: counter=(0,p); bits=o0^o1
__device__ __forceinline__ uint32_t pbits(uint32_t k0, uint32_t k1, uint32_t p) {
    uint32_t o0, o1;
    tf2x32(k0, k1, 0u, p, o0, o1);
    return o0 ^ o1;
}

__device__ __forceinline__ float bits_to_uniform(uint32_t bits) {
    return __fsub_rn(__uint_as_float((bits >> 9) | 0x3f800000u), 1.0f);
}

// ---------------------------------------------------------------------------
// Mask reset (must precede init_kernel: init atomically clears zero bits)
// ---------------------------------------------------------------------------
__global__ void premask_kernel() {
    int t = threadIdx.x;
    if (t < NBY) {
        g_chmask[2][t] = ~0ull;   // prev parity of iter 0 -> force all tiles
        g_chmask[0][t] = 0ull;
        g_chmask[1][t] = 0ull;
        g_posmask[t]   = 0ull;
        g_zeromask[t]  = ~0ull;
    }
}

// ---------------------------------------------------------------------------
// x0 = seed * habitat * goodness; clear zero-bit for tiles with any x0 != 0
// ---------------------------------------------------------------------------
__global__ void init_kernel(const float* __restrict__ seed,
                            const float* __restrict__ hab,
                            const float* __restrict__ good,
                            float* __restrict__ xout) {
    int idx = blockIdx.x * blockDim.x + threadIdx.x;
    if (idx < NPIX / 4) {
        const float4 s = ((const float4*)seed)[idx];
        const float4 h = ((const float4*)hab)[idx];
        const float4 g = ((const float4*)good)[idx];
        float4 o;
        o.x = __fmul_rn(__fmul_rn(s.x, h.x), g.x);
        o.y = __fmul_rn(__fmul_rn(s.y, h.y), g.y);
        o.z = __fmul_rn(__fmul_rn(s.z, h.z), g.z);
        o.w = __fmul_rn(__fmul_rn(s.w, h.w), g.w);
        ((float4*)xout)[idx] = o;
        if (o.x != 0.0f || o.y != 0.0f || o.z != 0.0f || o.w != 0.0f) {
            int pix = idx * 4;
            int by = (pix / WW) / TH;
            int bx = (pix % WW) / TW;      // 4 consecutive cols stay in one tile
            atomicAnd(&g_zeromask[by], ~(1ull << bx));
        }
    }
}

// ---------------------------------------------------------------------------
// One spread step. Each block owns 4 adjacent tiles in one tile-row.
//   y1 = x * (0.9999 + 1e-4*u1); y2 = maxpool3x3(y1); y3 = y2*(u2>0.5);
//   y4 = y3*goodness; x' = max(y4*((y4-x) > 0.05), x)
// Skip hierarchy (all exact, since good<1 and noise factor <= 1):
//   need (tile masks) -> zero-tile ring test -> pretest M-x>0.05 (no good
//   load) -> exact pos test -> RNG only on pos/dilated-pos cells.
// ---------------------------------------------------------------------------
__global__ __launch_bounds__(256)
void step_kernel(const float* __restrict__ xin, float* __restrict__ xout,
                 const float* __restrict__ good,
                 uint32_t k1a, uint32_t k1b, uint32_t k2a, uint32_t k2b,
                 int prev, int cur, int nxt) {
    __shared__ float xs[SH][SW];     // raw x (tile + halo)
    __shared__ float ys[SH][SW];     // noised x (maxpool operand)
    __shared__ unsigned s_rowpos[TH];

    const int tid = threadIdx.x;
    const int tx = tid & 31;
    const int ty = tid >> 5;                     // 0..7

    // zero the next-parity mask row (not read or written this launch)
    if (blockIdx.x < NBY && tid == 0) g_chmask[nxt][blockIdx.x] = 0ull;

    const int tbase = blockIdx.x * TILES_PER_BLOCK;
    const int by  = tbase >> 6;
    const int bx0 = tbase & 63;

    // uniform mask loads (LDG broadcast; shared by all 4 tiles)
    ull nbm = g_chmask[prev][by];
    const ull chm = nbm;
    if (by > 0)       nbm |= g_chmask[prev][by - 1];
    if (by < NBY - 1) nbm |= g_chmask[prev][by + 1];
    const ull posw  = g_posmask[by];
    const ull zerow = g_zeromask[by];            // own-tile bits owned by us

    #pragma unroll
    for (int kt = 0; kt < TILES_PER_BLOCK; kt++) {
        const int bx = bx0 + kt;
        const ull colm = (bx == 0) ? 3ull : (7ull << (bx - 1));
        const bool need = ((nbm & colm) != 0ull) || (((posw >> bx) & 1ull) != 0ull);
        if (!need) continue;                     // uniform across block

        const int selfchg = (int)((chm >> bx) & 1ull);
        const bool zb = ((zerow >> bx) & 1ull) != 0ull;
        const int c0 = bx * TW, r0 = by * TH;

        __syncthreads();                         // smem reuse barrier

        if (zb) {
            // ==== zero tile: interior is 0 by invariant; load ring only ====
            #pragma unroll
            for (int k = 0; k < 2; k++)
                xs[1 + ty + k * 8][1 + tx] = 0.0f;
            bool ringhit = false;
            if (tid < NRING) {
                int j, i;
                if (tid < SW)            { j = 0;      i = tid; }
                else if (tid < 2 * SW)   { j = SH - 1; i = tid - SW; }
                else { int t2 = tid - 2 * SW; j = 1 + (t2 >> 1); i = (t2 & 1) ? SW - 1 : 0; }
                int r = r0 - 1 + j, c = c0 - 1 + i;
                bool ok = (r >= 0) && (r < HH) && (c >= 0) && (c < WW);
                float v = ok ? xin[r * WW + c] : 0.0f;
                xs[j][i] = v;
                // v <= 0.05 => fmul(v,good) <= v <= 0.05 => no ignition
                ringhit = v > 0.05f;
            }
            int ringany = __syncthreads_or(ringhit ? 1 : 0);
            if (!ringany) {
                // tile stays all-zero this iter; write zeros only at iter 0
                if (selfchg) {
                    #pragma unroll
                    for (int k = 0; k < 2; k++) {
                        int r = r0 + ty + k * 8, c = c0 + tx;
                        xout[r * WW + c] = 0.0f;
                    }
                }
                continue;
            }
        } else {
            // ==== load raw x tile + halo ====
            #pragma unroll
            for (int k = 0; k < 3; k++) {
                int s = tid + k * 256;
                if (s < NSLOT) {
                    int j = s / SW, ii = s % SW;
                    int r = r0 - 1 + j, c = c0 - 1 + ii;
                    bool ok = (r >= 0) && (r < HH) && (c >= 0) && (c < WW);
                    xs[j][ii] = ok ? xin[r * WW + c] : 0.0f;
                }
            }
            __syncthreads();
        }

        // ==== pretest: M - x > 0.05 (no good load; pos => pre) ====
        float xx[2], M[2];
        bool  pre[2];
        #pragma unroll
        for (int k = 0; k < 2; k++) {
            int jj = 1 + ty + k * 8, ii = 1 + tx;
            float m = xs[jj - 1][ii - 1];
            m = fmaxf(m, xs[jj - 1][ii    ]);
            m = fmaxf(m, xs[jj - 1][ii + 1]);
            m = fmaxf(m, xs[jj    ][ii - 1]);
            m = fmaxf(m, xs[jj    ][ii    ]);
            m = fmaxf(m, xs[jj    ][ii + 1]);
            m = fmaxf(m, xs[jj + 1][ii - 1]);
            m = fmaxf(m, xs[jj + 1][ii    ]);
            m = fmaxf(m, xs[jj + 1][ii + 1]);
            M[k]  = m;
            xx[k] = xs[jj][ii];
            pre[k] = __fsub_rn(m, xx[k]) > 0.05f;
        }
        int anyPre = __syncthreads_or((pre[0] || pre[1]) ? 1 : 0);

        float gd[2];
        bool  pos[2] = {false, false};
        int   any = 0;
        if (anyPre) {
            // ==== exact pos test (loads good) ====
            #pragma unroll
            for (int k = 0; k < 2; k++) {
                int jj = 1 + ty + k * 8, ii = 1 + tx;
                int r = r0 + jj - 1, c = c0 + ii - 1;
                gd[k] = good[r * WW + c];
                pos[k] = pre[k] &&
                         (__fsub_rn(__fmul_rn(M[k], gd[k]), xx[k]) > 0.05f);
                unsigned rowmask = __ballot_sync(0xffffffffu, pos[k]);
                if (tx == 0) s_rowpos[ty + k * 8] = rowmask;
            }
            any = __syncthreads_or((pos[0] || pos[1]) ? 1 : 0);
        }

        if (!any) {
            // no update possible -> refresh out buffer only if stale
            if (selfchg) {
                #pragma unroll
                for (int k = 0; k < 2; k++) {
                    int jj = 1 + ty + k * 8, ii = 1 + tx;
                    int r = r0 + jj - 1, c = c0 + ii - 1;
                    xout[r * WW + c] = xx[k];
                }
            }
            if (tid == 0 && ((posw >> bx) & 1ull))
                atomicAnd(&g_posmask[by], ~(1ull << bx));
            continue;
        }

        // ==== fill noised tile, cipher gated on pos-mask dilated 1 px ====
        #pragma unroll
        for (int k = 0; k < 3; k++) {
            int s = tid + k * 256;
            bool sv = s < NSLOT;
            int ss = sv ? s : 0;
            int j = ss / SW, ii = ss % SW;
            float x = sv ? xs[j][ii] : 0.0f;
            unsigned rm = 0;
            #pragma unroll
            for (int dr = 0; dr < 3; dr++) {
                int cr = j - 2 + dr;
                if (cr >= 0 && cr < TH) rm |= s_rowpos[cr];
            }
            ull rm2 = ((ull)rm) << 2;
            bool needc = (((rm2 >> ii) & 7ull) != 0ull) && (x > 0.0f);
            float y1 = 0.0f;
            if (__ballot_sync(0xffffffffu, needc)) {
                int r = r0 - 1 + j, c = c0 - 1 + ii;
                uint32_t p = (uint32_t)(min(max(r, 0), HH - 1) * WW +
                                        min(max(c, 0), WW - 1));
                float u = bits_to_uniform(pbits(k1a, k1b, p));
                float f = __fadd_rn(0.9999f, __fmul_rn(1e-4f, u));
                y1 = __fmul_rn(x, f);
            }
            if (sv) ys[j][ii] = y1;
        }
        __syncthreads();

        // ==== maxpool + coin (cipher gated on pos) + write ====
        int chg = 0;
        #pragma unroll
        for (int k = 0; k < 2; k++) {
            int jj = 1 + ty + k * 8, ii = 1 + tx;
            float m = ys[jj - 1][ii - 1];
            m = fmaxf(m, ys[jj - 1][ii    ]);
            m = fmaxf(m, ys[jj - 1][ii + 1]);
            m = fmaxf(m, ys[jj    ][ii - 1]);
            m = fmaxf(m, ys[jj    ][ii    ]);
            m = fmaxf(m, ys[jj    ][ii + 1]);
            m = fmaxf(m, ys[jj + 1][ii - 1]);
            m = fmaxf(m, ys[jj + 1][ii    ]);
            m = fmaxf(m, ys[jj + 1][ii + 1]);

            int r = r0 + jj - 1, c = c0 + ii - 1;
            uint32_t p = (uint32_t)(r * WW + c);
            float y4 = 0.0f;
            if (__ballot_sync(0xffffffffu, pos[k])) {
                uint32_t bits = pbits(k2a, k2b, p);
                bool coin = ((bits >> 9) > 0x400000u);   // u > 0.5 strictly
                if (coin && m > 0.0f) y4 = __fmul_rn(m, gd[k]);
            }
            float d  = __fsub_rn(y4, xx[k]);
            float y5 = (d > 0.05f) ? y4 : 0.0f;
            float out = fmaxf(y5, xx[k]);
            xout[p] = out;
            chg |= (out != xx[k]) ? 1 : 0;
        }
        int anychg = __syncthreads_or(chg);
        if (tid == 0) {
            ull bit = 1ull << bx;
            if (anychg) {
                atomicOr(&g_chmask[cur][by], bit);
                if (zb) atomicAnd(&g_zeromask[by], ~bit);  // tile now nonzero
            }
            if (!((posw >> bx) & 1ull)) atomicOr(&g_posmask[by], bit);
        }
    }
}

// ---------------------------------------------------------------------------
// Host: per-iteration key schedule (fold_in + partitionable split), ping-pong
// data buffers, 3-parity changed masks. 102 launches total.
// ---------------------------------------------------------------------------
extern "C" void kernel_launch(void* const* d_in, const int* in_sizes, int n_in,
                              void* d_out, int out_size) {
    const float* seed = (const float*)d_in[0];
    const float* hab  = (const float*)d_in[1];
    const float* good = (const float*)d_in[2];
    float* xout = (float*)d_out;

    float* scratch = nullptr;
    cudaGetSymbolAddress((void**)&scratch, g_scratch);

    premask_kernel<<<1, 256>>>();
    init_kernel<<<(NPIX / 4 + 255) / 256, 256>>>(seed, hab, good, xout);

    for (int i = 0; i < 100; i++) {
        // fold_in(key(42)=(0,42), i) = cipher((0,42), (0,i))
        uint32_t f0, f1;
        tf2x32(0u, 42u, 0u, (uint32_t)i, f0, f1);
        // partitionable split: k1 = cipher(f,(0,0)), k2 = cipher(f,(0,1))
        uint32_t k1a, k1b, k2a, k2b;
        tf2x32(f0, f1, 0u, 0u, k1a, k1b);
        tf2x32(f0, f1, 0u, 1u, k2a, k2b);

        const int cur = i % 3, prev = (i + 2) % 3, nxt = (i + 1) % 3;
        const float* xin = (i & 1) ? scratch : xout;
        float*       xo  = (i & 1) ? xout    : scratch;

        step_kernel<<<STEP_GRID, 256>>>(xin, xo, good, k1a, k1b, k2a, k2b,
                                        prev, cur, nxt);
    }
    // i = 99 (odd) wrote into xout -> final state lands in d_out
}

// round 8
// speedup vs baseline: 1.0416x; 1.0416x over previous
#include <cuda_runtime.h>
#include <stdint.h>

#define HH 2048
#define WW 2048
#define NPIX (HH * WW)

#define TW 32
#define TH 16
#define SW2 (TW + 4)             // 36 (halo 2)
#define SH2 (TH + 4)             // 20
#define NSLOT2 (SW2 * SH2)       // 720
#define SWA (TW + 2)             // 34 (core+1 region)
#define SHA (TH + 2)             // 18
#define NSLOTA (SWA * SHA)       // 612

#define NBX 64                   // tiles per row (bits in a mask word)
#define NBY 128                  // tile rows
#define NB  (NBX * NBY)          // 8192
#define TILES_PER_BLOCK 2
#define STEP_GRID (NB / TILES_PER_BLOCK)   // 4096

typedef unsigned long long ull;

__device__ float g_scratch[NPIX];
__device__ ull g_chmask[3][NBY];   // changed bits, 3-parity rotation
__device__ ull g_posmask[NBY];     // possible bits

// ---------------------------------------------------------------------------
// Threefry-2x32, 20 rounds — exact transcription of jax._src.prng
// ---------------------------------------------------------------------------
__host__ __device__ __forceinline__ uint32_t rotl32(uint32_t v, uint32_t r) {
#ifdef __CUDA_ARCH__
    return __funnelshift_l(v, v, r);
#else
    return (v << r) | (v >> (32u - r));
#endif
}

__host__ __device__ __forceinline__ void tf2x32(uint32_t k0, uint32_t k1,
                                                uint32_t x0, uint32_t x1,
                                                uint32_t& o0, uint32_t& o1) {
    uint32_t ks2 = k0 ^ k1 ^ 0x1BD11BDAu;
    x0 += k0; x1 += k1;
#define TF_R(r) { x0 += x1; x1 = rotl32(x1, r); x1 ^= x0; }
    TF_R(13u) TF_R(15u) TF_R(26u) TF_R(6u)
    x0 += k1;  x1 += ks2 + 1u;
    TF_R(17u) TF_R(29u) TF_R(16u) TF_R(24u)
    x0 += ks2; x1 += k0 + 2u;
    TF_R(13u) TF_R(15u) TF_R(26u) TF_R(6u)
    x0 += k0;  x1 += k1 + 3u;
    TF_R(17u) TF_R(29u) TF_R(16u) TF_R(24u)
    x0 += k1;  x1 += ks2 + 4u;
    TF_R(13u) TF_R(15u) TF_R(26u) TF_R(6u)
    x0 += ks2; x1 += k0 + 5u;
#undef TF_R
    o0 = x0; o1 = x1;
}

// Partitionable-mode random bits for flat index p: counter=(0,p); bits=o0^o1
__device__ __forceinline__ uint32_t pbits(uint32_t k0, uint32_t k1, uint32_t p) {
    uint32_t o0, o1;
    tf2x32(k0, k1, 0u, p, o0, o1);
    return o0 ^ o1;
}

__device__ __forceinline__ float bits_to_uniform(uint32_t bits) {
    return __fsub_rn(__uint_as_float((bits >> 9) | 0x3f800000u), 1.0f);
}

#define MAX9(A, a, b, m) do {                                   \
    m = A[a][b];                                                \
    m = fmaxf(m, A[a][b + 1]);   m = fmaxf(m, A[a][b + 2]);     \
    m = fmaxf(m, A[a + 1][b]);   m = fmaxf(m, A[a + 1][b + 1]); \
    m = fmaxf(m, A[a + 1][b + 2]);                              \
    m = fmaxf(m, A[a + 2][b]);   m = fmaxf(m, A[a + 2][b + 1]); \
    m = fmaxf(m, A[a + 2][b + 2]); } while (0)

// ---------------------------------------------------------------------------
// x0 = seed * habitat * goodness  (+ reset masks)
// ---------------------------------------------------------------------------
__global__ void init_kernel(const float* __restrict__ seed,
                            const float* __restrict__ hab,
                            const float* __restrict__ good,
                            float* __restrict__ xout) {
    int idx = blockIdx.x * blockDim.x + threadIdx.x;
    if (idx < NPIX / 4) {
        const float4 s = ((const float4*)seed)[idx];
        const float4 h = ((const float4*)hab)[idx];
        const float4 g = ((const float4*)good)[idx];
        float4 o;
        o.x = __fmul_rn(__fmul_rn(s.x, h.x), g.x);
        o.y = __fmul_rn(__fmul_rn(s.y, h.y), g.y);
        o.z = __fmul_rn(__fmul_rn(s.z, h.z), g.z);
        o.w = __fmul_rn(__fmul_rn(s.w, h.w), g.w);
        ((float4*)xout)[idx] = o;
    }
    if (idx < NBY) {
        g_chmask[2][idx] = ~0ull;   // prev parity of launch 0 -> force all
        g_chmask[0][idx] = 0ull;
        g_chmask[1][idx] = 0ull;
        g_posmask[idx]   = 0ull;
    }
}

// ---------------------------------------------------------------------------
// TWO fused spread iterations per launch. Halo-2 tile; iter A computed on
// core+1 (ring values recomputed identically to neighbors — same RNG keys,
// same per-pixel counters), iter B on core. One read + one write of x per
// 2 reference iterations.
// ---------------------------------------------------------------------------
__global__ __launch_bounds__(256)
void step2_kernel(const float* __restrict__ xin, float* __restrict__ xout,
                  const float* __restrict__ good,
                  uint32_t kA1a, uint32_t kA1b, uint32_t kA2a, uint32_t kA2b,
                  uint32_t kB1a, uint32_t kB1b, uint32_t kB2a, uint32_t kB2b,
                  int prev, int cur, int nxt) {
    __shared__ float xs[SH2][SW2];   // x at iter start (tile + halo2)
    __shared__ float ys[SH2][SW2];   // noised values (A: full; B: core+1 sub)
    __shared__ float xa[SHA][SWA];   // x after iter A (core+1)
    __shared__ float gs[SHA][SWA];   // goodness (core+1)
    __shared__ ull s_posA[SHA];
    __shared__ unsigned s_rowposB[TH];

    const int tid = threadIdx.x;
    const int tx = tid & 31;
    const int ty = tid >> 5;                     // 0..7

    if (blockIdx.x < NBY && tid == 0) g_chmask[nxt][blockIdx.x] = 0ull;

    const int tbase = blockIdx.x * TILES_PER_BLOCK;
    const int by  = tbase >> 6;
    const int bx0 = tbase & 63;

    ull nbm = g_chmask[prev][by];
    const ull chm = nbm;
    if (by > 0)       nbm |= g_chmask[prev][by - 1];
    if (by < NBY - 1) nbm |= g_chmask[prev][by + 1];
    const ull posw = g_posmask[by];

    #pragma unroll
    for (int kt = 0; kt < TILES_PER_BLOCK; kt++) {
        const int bx = bx0 + kt;
        const ull colm = (bx == 0) ? 3ull : (7ull << (bx - 1));
        const bool need = ((nbm & colm) != 0ull) || (((posw >> bx) & 1ull) != 0ull);
        if (!need) continue;                     // uniform across block

        const int selfchg = (int)((chm >> bx) & 1ull);
        const int c0 = bx * TW, r0 = by * TH;

        __syncthreads();                         // smem reuse barrier

        // ==== load x tile + halo2; zero posA masks ====
        #pragma unroll
        for (int q = 0; q < 3; q++) {
            int s = tid + q * 256;
            if (s < NSLOT2) {
                int j = s / SW2, i = s % SW2;
                int r = r0 - 2 + j, c = c0 - 2 + i;
                bool ok = (r >= 0) && (r < HH) && (c >= 0) && (c < WW);
                xs[j][i] = ok ? xin[r * WW + c] : 0.0f;
            }
        }
        if (tid < SHA) s_posA[tid] = 0ull;
        __syncthreads();

        // ==== iter A pos pass over core+1 (also loads good) ====
        bool posAv[3]; float xxA[3], gsv[3];
        #pragma unroll
        for (int q = 0; q < 3; q++) {
            int s = tid + q * 256;
            bool sv = s < NSLOTA;
            posAv[q] = false; xxA[q] = 0.0f; gsv[q] = 0.0f;
            if (sv) {
                int a = s / SWA, b = s % SWA;
                int r = r0 - 1 + a, c = c0 - 1 + b;
                bool inim = (r >= 0) && (r < HH) && (c >= 0) && (c < WW);
                float g = inim ? good[r * WW + c] : 0.0f;
                gsv[q] = g; gs[a][b] = g;
                float x = xs[a + 1][b + 1];
                xxA[q] = x;
                float M; MAX9(xs, a, b, M);
                if (inim && (__fsub_rn(__fmul_rn(M, g), x) > 0.05f)) {
                    posAv[q] = true;
                    atomicOr(&s_posA[a], 1ull << b);
                }
            }
        }
        int anyA = __syncthreads_or((posAv[0] || posAv[1] || posAv[2]) ? 1 : 0);

        if (!anyA) {
            // both sub-iterations are no-ops -> refresh buffer only if stale
            if (selfchg) {
                #pragma unroll
                for (int k = 0; k < 2; k++) {
                    int rr = ty + k * 8, cc = tx;
                    xout[(r0 + rr) * WW + (c0 + cc)] = xs[rr + 2][cc + 2];
                }
            }
            if (tid == 0 && ((posw >> bx) & 1ull))
                atomicAnd(&g_posmask[by], ~(1ull << bx));
            continue;
        }

        // ==== iter A noise over full halo2 region (gated, pos dilated 1) ====
        #pragma unroll
        for (int q = 0; q < 3; q++) {
            int s = tid + q * 256;
            bool sv = s < NSLOT2;
            int j = sv ? s / SW2 : 0, i = sv ? s % SW2 : 0;
            float x = sv ? xs[j][i] : 0.0f;
            ull rm = 0ull;
            #pragma unroll
            for (int dr = 0; dr < 3; dr++) {
                int ar = j - 2 + dr;
                if (ar >= 0 && ar < SHA) rm |= s_posA[ar];
            }
            ull rm2 = rm << 2;
            bool needc = (((rm2 >> i) & 7ull) != 0ull) && (x > 0.0f);
            float y1 = 0.0f;
            if (__ballot_sync(0xffffffffu, needc)) {
                int r = r0 - 2 + j, c = c0 - 2 + i;
                uint32_t p = (uint32_t)(min(max(r, 0), HH - 1) * WW +
                                        min(max(c, 0), WW - 1));
                float u = bits_to_uniform(pbits(kA1a, kA1b, p));
                float f = __fadd_rn(0.9999f, __fmul_rn(1e-4f, u));
                y1 = __fmul_rn(x, f);
            }
            if (sv) ys[j][i] = y1;
        }
        __syncthreads();

        // ==== iter A update over core+1 -> xa ====
        #pragma unroll
        for (int q = 0; q < 3; q++) {
            int s = tid + q * 256;
            bool sv = s < NSLOTA;
            int a = sv ? s / SWA : 0, b = sv ? s % SWA : 0;
            float m; MAX9(ys, a, b, m);
            float y4 = 0.0f;
            if (__ballot_sync(0xffffffffu, posAv[q])) {
                int r = r0 - 1 + a, c = c0 - 1 + b;
                uint32_t p = (uint32_t)(min(max(r, 0), HH - 1) * WW +
                                        min(max(c, 0), WW - 1));
                uint32_t bits = pbits(kA2a, kA2b, p);
                bool coin = ((bits >> 9) > 0x400000u);   // u > 0.5 strictly
                if (coin && m > 0.0f) y4 = __fmul_rn(m, gsv[q]);
            }
            float d  = __fsub_rn(y4, xxA[q]);
            float y5 = (d > 0.05f) ? y4 : 0.0f;
            if (sv) xa[a][b] = fmaxf(y5, xxA[q]);
        }
        __syncthreads();

        // ==== iter B pos pass over core ====
        bool posB[2]; float xab[2], gdB[2];
        #pragma unroll
        for (int k = 0; k < 2; k++) {
            int rr = ty + k * 8, cc = tx;
            float M; MAX9(xa, rr, cc, M);
            xab[k] = xa[rr + 1][cc + 1];
            gdB[k] = gs[rr + 1][cc + 1];
            posB[k] = __fsub_rn(__fmul_rn(M, gdB[k]), xab[k]) > 0.05f;
            unsigned rowmask = __ballot_sync(0xffffffffu, posB[k]);
            if (tx == 0) s_rowposB[rr] = rowmask;
        }
        int anyB = __syncthreads_or((posB[0] || posB[1]) ? 1 : 0);

        if (!anyB) {
            // iter B is a no-op; final = xa core. Executed tile -> write.
            int chg = 0;
            #pragma unroll
            for (int k = 0; k < 2; k++) {
                int rr = ty + k * 8, cc = tx;
                float out = xab[k];
                xout[(r0 + rr) * WW + (c0 + cc)] = out;
                chg |= (out != xs[rr + 2][cc + 2]) ? 1 : 0;
            }
            int anychg = __syncthreads_or(chg);
            if (tid == 0) {
                if (anychg) atomicOr(&g_chmask[cur][by], 1ull << bx);
                if ((posw >> bx) & 1ull)
                    atomicAnd(&g_posmask[by], ~(1ull << bx));
            }
            continue;
        }

        // ==== iter B noise over core+1 (reuse ys sub-array; reads xa) ====
        #pragma unroll
        for (int q = 0; q < 3; q++) {
            int s = tid + q * 256;
            bool sv = s < NSLOTA;
            int a = sv ? s / SWA : 0, b = sv ? s % SWA : 0;
            float x = sv ? xa[a][b] : 0.0f;
            unsigned rm = 0;
            #pragma unroll
            for (int dr = 0; dr < 3; dr++) {
                int br = a - 2 + dr;
                if (br >= 0 && br < TH) rm |= s_rowposB[br];
            }
            ull rm2 = ((ull)rm) << 2;
            bool needc = (((rm2 >> b) & 7ull) != 0ull) && (x > 0.0f);
            float y1 = 0.0f;
            if (__ballot_sync(0xffffffffu, needc)) {
                int r = r0 - 1 + a, c = c0 - 1 + b;
                uint32_t p = (uint32_t)(min(max(r, 0), HH - 1) * WW +
                                        min(max(c, 0), WW - 1));
                float u = bits_to_uniform(pbits(kB1a, kB1b, p));
                float f = __fadd_rn(0.9999f, __fmul_rn(1e-4f, u));
                y1 = __fmul_rn(x, f);
            }
            if (sv) ys[a][b] = y1;
        }
        __syncthreads();

        // ==== iter B final over core + write ====
        int chg = 0;
        #pragma unroll
        for (int k = 0; k < 2; k++) {
            int rr = ty + k * 8, cc = tx;
            float m; MAX9(ys, rr, cc, m);
            uint32_t p = (uint32_t)((r0 + rr) * WW + (c0 + cc));
            float y4 = 0.0f;
            if (__ballot_sync(0xffffffffu, posB[k])) {
                uint32_t bits = pbits(kB2a, kB2b, p);
                bool coin = ((bits >> 9) > 0x400000u);   // u > 0.5 strictly
                if (coin && m > 0.0f) y4 = __fmul_rn(m, gdB[k]);
            }
            float d  = __fsub_rn(y4, xab[k]);
            float y5 = (d > 0.05f) ? y4 : 0.0f;
            float out = fmaxf(y5, xab[k]);
            xout[p] = out;
            chg |= (out != xs[rr + 2][cc + 2]) ? 1 : 0;
        }
        int anychg = __syncthreads_or(chg);
        if (tid == 0) {
            ull bit = 1ull << bx;
            if (anychg) atomicOr(&g_chmask[cur][by], bit);
            if (!((posw >> bx) & 1ull)) atomicOr(&g_posmask[by], bit);
        }
    }
}

// ---------------------------------------------------------------------------
// Host: 50 fused launches; keys for iters 2t and 2t+1 per launch.
// ---------------------------------------------------------------------------
extern "C" void kernel_launch(void* const* d_in, const int* in_sizes, int n_in,
                              void* d_out, int out_size) {
    const float* seed = (const float*)d_in[0];
    const float* hab  = (const float*)d_in[1];
    const float* good = (const float*)d_in[2];
    float* xout = (float*)d_out;

    float* scratch = nullptr;
    cudaGetSymbolAddress((void**)&scratch, g_scratch);

    init_kernel<<<(NPIX / 4 + 255) / 256, 256>>>(seed, hab, good, xout);

    for (int t = 0; t < 50; t++) {
        uint32_t kk[2][4];
        for (int s = 0; s < 2; s++) {
            int i = 2 * t + s;
            uint32_t f0, f1;
            tf2x32(0u, 42u, 0u, (uint32_t)i, f0, f1);           // fold_in
            tf2x32(f0, f1, 0u, 0u, kk[s][0], kk[s][1]);         // split k1
            tf2x32(f0, f1, 0u, 1u, kk[s][2], kk[s][3]);         // split k2
        }
        const int cur = t % 3, prev = (t + 2) % 3, nxt = (t + 1) % 3;
        const float* xin = (t & 1) ? scratch : xout;
        float*       xo  = (t & 1) ? xout    : scratch;

        step2_kernel<<<STEP_GRID, 256>>>(xin, xo, good,
                                         kk[0][0], kk[0][1], kk[0][2], kk[0][3],
                                         kk[1][0], kk[1][1], kk[1][2], kk[1][3],
                                         prev, cur, nxt);
    }
    // t = 49 (odd) wrote into xout -> final state lands in d_out
}